// round 1
// baseline (speedup 1.0000x reference)
#include <cuda_runtime.h>
#include <math.h>

// Problem constants (fixed by setup_inputs)
#define C_TOT   2048
#define HW2     196          // 14*14
#define O_TOT   48           // 32 conv maps + 8 (fc first half) + 8 (fc second half)
#define CSPLIT  4
#define C_PER   (C_TOT / CSPLIT)   // 512
#define CC      128                // c-chunk staged in smem
#define NCHUNK  (C_PER / CC)       // 4
#define O_PER   24                 // o-split: 2 blocks of 24
#define ROWSTR  52                 // smem row stride in floats (48 data + pad, 208B = 13*16)
#define MAXB    64

// Scratch: partial GEMM outputs per c-split: [CSPLIT][B][48][196]  (~9.6 MB)
__device__ float g_partial[(size_t)CSPLIT * MAXB * O_TOT * HW2];

__device__ __forceinline__ unsigned long long pack2(float a, float b) {
    unsigned long long r;
    unsigned int ia = __float_as_uint(a), ib = __float_as_uint(b);
    asm("mov.b64 %0, {%1, %2};" : "=l"(r) : "r"(ia), "r"(ib));
    return r;
}
__device__ __forceinline__ void ffma2(unsigned long long& d, unsigned long long a,
                                      unsigned long long b) {
    asm("fma.rn.f32x2 %0, %1, %2, %0;" : "+l"(d) : "l"(a), "l"(b));
}
__device__ __forceinline__ float unpack_sum(unsigned long long v) {
    unsigned int lo, hi;
    asm("mov.b64 {%0, %1}, %2;" : "=r"(lo), "=r"(hi) : "l"(v));
    return __uint_as_float(lo) + __uint_as_float(hi);
}

// ---------------------------------------------------------------------------
// Kernel A: fused 48-column GEMM over x.
// Grid: (ceil(B*196/128), 2 o-splits, 4 c-splits), 128 threads.
// Each thread owns one (b, hw) position; accumulates 24 outputs in f32x2
// pairs over consecutive channels (even c in .lo, odd c in .hi).
// ---------------------------------------------------------------------------
__global__ void __launch_bounds__(128, 4) wsl_gemm_kernel(
    const float* __restrict__ x,
    const float* __restrict__ down_w,
    const float* __restrict__ fc_w,
    int B)
{
    __shared__ __align__(16) float sw[(CC / 2) * ROWSTR];  // 64 rows * 52 floats

    const int tid   = threadIdx.x;
    const int obase = blockIdx.y * O_PER;
    const int cbase = blockIdx.z * C_PER;
    const int p     = blockIdx.x * 128 + tid;
    const int npos  = B * HW2;
    const bool valid = (p < npos);
    const int pc = valid ? p : 0;
    const int b  = pc / HW2;
    const int hw = pc % HW2;

    unsigned long long acc[O_PER];
#pragma unroll
    for (int i = 0; i < O_PER; i++) acc[i] = 0ull;

    for (int ch = 0; ch < NCHUNK; ch++) {
        const int c0 = cbase + ch * CC;
        // Stage 24 x 128 weights as interleaved c-pairs: row cp holds
        // [w(o0,2cp), w(o0,2cp+1), w(o1,2cp), ...]
#pragma unroll
        for (int k = 0; k < (O_PER * CC) / 128; k++) {   // 24 iters
            int idx = tid + k * 128;
            int oo  = idx >> 7;           // / CC
            int cc  = idx & (CC - 1);
            int o   = obase + oo;
            int c   = c0 + cc;
            float w;
            if (o < 32)      w = down_w[o * C_TOT + c];
            else if (o < 40) w = fc_w[(o - 32) * (2 * C_TOT) + c];
            else             w = fc_w[(o - 40) * (2 * C_TOT) + C_TOT + c];
            sw[(cc >> 1) * ROWSTR + (oo << 1) + (cc & 1)] = w;
        }
        __syncthreads();

        const float* xp = x + ((long long)b * C_TOT + c0) * HW2 + hw;
#pragma unroll 4
        for (int cp = 0; cp < CC / 2; cp++) {
            float xa = __ldg(xp + (2 * cp) * HW2);
            float xb = __ldg(xp + (2 * cp + 1) * HW2);
            unsigned long long xv = pack2(xa, xb);
            const ulonglong2* wr = (const ulonglong2*)(sw + cp * ROWSTR);
#pragma unroll
            for (int oq = 0; oq < O_PER / 2; oq++) {
                ulonglong2 wv = wr[oq];
                ffma2(acc[2 * oq],     xv, wv.x);
                ffma2(acc[2 * oq + 1], xv, wv.y);
            }
        }
        __syncthreads();
    }

    if (valid) {
        float* dst = g_partial +
            ((size_t)(blockIdx.z * MAXB + b) * O_TOT + obase) * HW2 + hw;
#pragma unroll
        for (int oo = 0; oo < O_PER; oo++) {
            dst[oo * HW2] = unpack_sum(acc[oo]);
        }
    }
}

// ---------------------------------------------------------------------------
// Kernel B: per-batch epilogue. One CTA (256 thr) per batch element.
//   xc[o][hw] = sum of csplit partials (+ down_b for o<32)
//   gmp/scores/log-softmax -> x_out
//   sal[hw] = (1/32) sum_j x_out[j] * sum_m xc[4j+m][hw]
//   logits2[j] = (P1[j] + P2[j])/196 + fc_b[j];  P1 = sum_hw t1, P2 = sum_hw sal*t2
// ---------------------------------------------------------------------------
__global__ void __launch_bounds__(256) wsl_final_kernel(
    const float* __restrict__ down_b,
    const float* __restrict__ fc_b,
    float* __restrict__ out,
    int B)
{
    __shared__ float xc[O_TOT * HW2];     // 48*196
    __shared__ float gmp[32];
    __shared__ float xout[8];
    __shared__ float red[16 * 8];         // [16 values][8 warps]
    __shared__ float psum[16];            // p1[0..7], p2[8..15]

    const int b = blockIdx.x;
    const int tid = threadIdx.x;

    // Sum c-split partials; add conv bias for o<32.
    for (int i = tid; i < O_TOT * HW2; i += 256) {
        int o = i / HW2;
        float s = 0.f;
#pragma unroll
        for (int cs = 0; cs < CSPLIT; cs++)
            s += g_partial[((size_t)(cs * MAXB + b) * O_TOT) * HW2 + i];
        if (o < 32) s += down_b[o];
        xc[i] = s;
    }
    __syncthreads();

    // Global max pool per conv map.
    if (tid < 32) {
        float m = -INFINITY;
        for (int hw = 0; hw < HW2; hw++) m = fmaxf(m, xc[tid * HW2 + hw]);
        gmp[tid] = m;
    }
    __syncthreads();

    // scores -> log_softmax -> x_out (first output)
    if (tid == 0) {
        float sc[8];
        float mx = -INFINITY;
        for (int j = 0; j < 8; j++) {
            sc[j] = 0.25f * (gmp[4 * j] + gmp[4 * j + 1] + gmp[4 * j + 2] + gmp[4 * j + 3]);
            mx = fmaxf(mx, sc[j]);
        }
        float se = 0.f;
        for (int j = 0; j < 8; j++) se += expf(sc[j] - mx);
        float lse = mx + logf(se);
        for (int j = 0; j < 8; j++) {
            float v = sc[j] - lse;
            xout[j] = v;
            out[(size_t)b * 8 + j] = v;
        }
    }
    __syncthreads();

    // Saliency + the two 8-wide reductions over hw.
    float v[16];
    if (tid < HW2) {
        float sal = 0.f;
#pragma unroll
        for (int j = 0; j < 8; j++) {
            float cls = xc[(4 * j) * HW2 + tid] + xc[(4 * j + 1) * HW2 + tid] +
                        xc[(4 * j + 2) * HW2 + tid] + xc[(4 * j + 3) * HW2 + tid];
            sal += xout[j] * cls;
        }
        sal *= (1.f / 32.f);
#pragma unroll
        for (int j = 0; j < 8; j++) {
            v[j]     = xc[(32 + j) * HW2 + tid];        // t1
            v[8 + j] = sal * xc[(40 + j) * HW2 + tid];  // sal * t2
        }
    } else {
#pragma unroll
        for (int k = 0; k < 16; k++) v[k] = 0.f;
    }
    // Warp tree-reduce (all 256 threads participate; inactive lanes are zero).
#pragma unroll
    for (int off = 16; off > 0; off >>= 1) {
#pragma unroll
        for (int k = 0; k < 16; k++)
            v[k] += __shfl_down_sync(0xffffffffu, v[k], off);
    }
    const int w = tid >> 5, lane = tid & 31;
    if (lane == 0) {
#pragma unroll
        for (int k = 0; k < 16; k++) red[k * 8 + w] = v[k];
    }
    __syncthreads();
    if (tid < 16) {
        float s = 0.f;
#pragma unroll
        for (int ww = 0; ww < 8; ww++) s += red[tid * 8 + ww];
        psum[tid] = s;
    }
    __syncthreads();

    // logits2 -> log_softmax -> x_conv_out (second output)
    if (tid == 0) {
        float lg[8];
        float mx = -INFINITY;
        for (int j = 0; j < 8; j++) {
            lg[j] = (psum[j] + psum[8 + j]) * (1.f / 196.f) + fc_b[j];
            mx = fmaxf(mx, lg[j]);
        }
        float se = 0.f;
        for (int j = 0; j < 8; j++) se += expf(lg[j] - mx);
        float lse = mx + logf(se);
        for (int j = 0; j < 8; j++)
            out[(size_t)B * 8 + (size_t)b * 8 + j] = lg[j] - lse;
    }
}

// ---------------------------------------------------------------------------
extern "C" void kernel_launch(void* const* d_in, const int* in_sizes, int n_in,
                              void* d_out, int out_size)
{
    const float* x      = (const float*)d_in[0];   // [B, 2048, 14, 14]
    const float* down_w = (const float*)d_in[1];   // [32, 2048]
    const float* down_b = (const float*)d_in[2];   // [32]
    const float* fc_w   = (const float*)d_in[3];   // [8, 4096]
    const float* fc_b   = (const float*)d_in[4];   // [8]
    float* out = (float*)d_out;                    // [2, B, 8] flattened tuple

    int B = in_sizes[0] / (C_TOT * HW2);           // 64

    dim3 gridA((B * HW2 + 127) / 128, 2 /*osplit*/, CSPLIT);
    wsl_gemm_kernel<<<gridA, 128>>>(x, down_w, fc_w, B);
    wsl_final_kernel<<<B, 256>>>(down_b, fc_b, out, B);
}

// round 3
// speedup vs baseline: 1.7108x; 1.7108x over previous
#include <cuda_runtime.h>
#include <cstdint>
#include <math.h>

// ---------------------------------------------------------------------------
// Problem constants
// ---------------------------------------------------------------------------
#define C_TOT   2048
#define HW2     196
#define O_REAL  48
#define MAXB    64
#define M_TOT   12544        // 64 * 196
#define M_TILE  64
#define MTILES  196          // M_TOT / M_TILE
#define KSPLIT  2
#define K_PER   (C_TOT / KSPLIT)   // 1024
#define KC      32
#define NCH     (K_PER / KC)       // 32

// K-split partial GEMM outputs: [KSPLIT][B][48][196]  (4.8 MB)
__device__ float g_part[(size_t)KSPLIT * MAXB * O_REAL * HW2];

// ---------------------------------------------------------------------------
// tf32 helpers
// ---------------------------------------------------------------------------
__device__ __forceinline__ uint32_t cvt_tf32(float v) {
    uint32_t r;
    asm("cvt.rna.tf32.f32 %0, %1;" : "=r"(r) : "f"(v));
    return r;
}

__device__ __forceinline__ void mma_tf32(float* c, const uint32_t* a,
                                         uint32_t b0, uint32_t b1) {
    asm volatile(
        "mma.sync.aligned.m16n8k8.row.col.f32.tf32.tf32.f32 "
        "{%0,%1,%2,%3}, {%4,%5,%6,%7}, {%8,%9}, {%0,%1,%2,%3};"
        : "+f"(c[0]), "+f"(c[1]), "+f"(c[2]), "+f"(c[3])
        : "r"(a[0]), "r"(a[1]), "r"(a[2]), "r"(a[3]), "r"(b0), "r"(b1));
}

// XOR swizzle: row-major [row][32] with k' = k ^ ((row&7)<<2)  (conflict-free)
#define SW(r, k) (((r) << 5) + ((k) ^ (((r) & 7) << 2)))

// SMEM (uint32 units): per buffer AH[64*32] AL[64*32] BH[48*32] BL[48*32]
#define AH_OFF  0
#define AL_OFF  2048
#define BH_OFF  4096
#define BL_OFF  5632
#define BUF_U32 7168
#define SMEM_BYTES (2 * BUF_U32 * 4)   // 57344

// ---------------------------------------------------------------------------
// Kernel A: tf32 3-split GEMM  part[ks][m][o] = sum_{k in split} x[m,k] W[o,k]
// Grid (196, 2), 128 threads. Warp w handles m rows [wid*16, wid*16+16).
// ---------------------------------------------------------------------------
__global__ void __launch_bounds__(128) wsl_mma_kernel(
    const float* __restrict__ x,
    const float* __restrict__ down_w,
    const float* __restrict__ fc_w)
{
    extern __shared__ __align__(16) uint32_t smem[];

    const int tid  = threadIdx.x;
    const int wid  = tid >> 5;
    const int lane = tid & 31;
    const int m_base  = blockIdx.x * M_TILE;
    const int ks_base = blockIdx.y * K_PER;

    // ---- per-thread staging descriptors ----
    // A: 4 quads (64 m x 8 kq), idx = tid + 128*i -> m = idx&63, kq = idx>>6
    const float* a_ptr[4];
    uint32_t a_sts[4];
    int a_kq[4];
#pragma unroll
    for (int i = 0; i < 4; i++) {
        int idx = tid + 128 * i;
        int am  = idx & 63;
        int akq = idx >> 6;
        int mg  = m_base + am;
        int bb  = mg / HW2;
        int hw  = mg - bb * HW2;
        a_ptr[i] = x + ((size_t)bb * C_TOT) * HW2 + hw;
        a_kq[i]  = akq;
        a_sts[i] = (uint32_t)((am << 5) + ((akq << 2) ^ ((am & 7) << 2)));
    }
    // B: 3 quads (48 n x 8 kq), idx = tid + 128*i -> n = idx>>3, kq = idx&7
    const float* b_ptr[3];
    uint32_t b_sts[3];
    int b_kq[3];
#pragma unroll
    for (int i = 0; i < 3; i++) {
        int idx = tid + 128 * i;
        int n   = idx >> 3;
        int kq  = idx & 7;
        const float* wr;
        if (n < 32)      wr = down_w + (size_t)n * C_TOT;
        else if (n < 40) wr = fc_w + (size_t)(n - 32) * (2 * C_TOT);
        else             wr = fc_w + (size_t)(n - 40) * (2 * C_TOT) + C_TOT;
        b_ptr[i] = wr;
        b_kq[i]  = kq;
        b_sts[i] = (uint32_t)((n << 5) + ((kq << 2) ^ ((n & 7) << 2)));
    }

    float acc[6][4];
#pragma unroll
    for (int t = 0; t < 6; t++)
#pragma unroll
        for (int j = 0; j < 4; j++) acc[t][j] = 0.f;

    // ---- staging lambdas (manual) ----
    float4 areg[4], breg[3];

    auto ldg_chunk = [&](int ch) {
        const int kb = ks_base + ch * KC;
#pragma unroll
        for (int i = 0; i < 4; i++) {
            const float* p = a_ptr[i] + (size_t)(kb + a_kq[i] * 4) * HW2;
            areg[i].x = __ldg(p);
            areg[i].y = __ldg(p + HW2);
            areg[i].z = __ldg(p + 2 * HW2);
            areg[i].w = __ldg(p + 3 * HW2);
        }
#pragma unroll
        for (int i = 0; i < 3; i++)
            breg[i] = *reinterpret_cast<const float4*>(b_ptr[i] + kb + b_kq[i] * 4);
    };

    auto sts_chunk = [&](uint32_t* buf) {
#pragma unroll
        for (int i = 0; i < 4; i++) {
            uint32_t h0 = cvt_tf32(areg[i].x), h1 = cvt_tf32(areg[i].y);
            uint32_t h2 = cvt_tf32(areg[i].z), h3 = cvt_tf32(areg[i].w);
            uint32_t l0 = cvt_tf32(areg[i].x - __uint_as_float(h0));
            uint32_t l1 = cvt_tf32(areg[i].y - __uint_as_float(h1));
            uint32_t l2 = cvt_tf32(areg[i].z - __uint_as_float(h2));
            uint32_t l3 = cvt_tf32(areg[i].w - __uint_as_float(h3));
            *reinterpret_cast<uint4*>(buf + AH_OFF + a_sts[i]) = make_uint4(h0, h1, h2, h3);
            *reinterpret_cast<uint4*>(buf + AL_OFF + a_sts[i]) = make_uint4(l0, l1, l2, l3);
        }
#pragma unroll
        for (int i = 0; i < 3; i++) {
            uint32_t h0 = cvt_tf32(breg[i].x), h1 = cvt_tf32(breg[i].y);
            uint32_t h2 = cvt_tf32(breg[i].z), h3 = cvt_tf32(breg[i].w);
            uint32_t l0 = cvt_tf32(breg[i].x - __uint_as_float(h0));
            uint32_t l1 = cvt_tf32(breg[i].y - __uint_as_float(h1));
            uint32_t l2 = cvt_tf32(breg[i].z - __uint_as_float(h2));
            uint32_t l3 = cvt_tf32(breg[i].w - __uint_as_float(h3));
            *reinterpret_cast<uint4*>(buf + BH_OFF + b_sts[i]) = make_uint4(h0, h1, h2, h3);
            *reinterpret_cast<uint4*>(buf + BL_OFF + b_sts[i]) = make_uint4(l0, l1, l2, l3);
        }
    };

    // prologue
    ldg_chunk(0);
    sts_chunk(smem);
    __syncthreads();

    const int mrow = lane >> 2;        // 0..7
    const int kcol = lane & 3;         // 0..3

    for (int ch = 0; ch < NCH; ch++) {
        if (ch + 1 < NCH) ldg_chunk(ch + 1);

        uint32_t* buf = smem + (ch & 1) * BUF_U32;
        const uint32_t* AH = buf + AH_OFF;
        const uint32_t* AL = buf + AL_OFF;
        const uint32_t* BH = buf + BH_OFF;
        const uint32_t* BL = buf + BL_OFF;
        const int mw = wid * 16;

#pragma unroll
        for (int s = 0; s < 4; s++) {
            const int k0 = s * 8 + kcol;
            uint32_t ah[4], al[4];
            ah[0] = AH[SW(mw + mrow,     k0)];
            ah[1] = AH[SW(mw + mrow + 8, k0)];
            ah[2] = AH[SW(mw + mrow,     k0 + 4)];
            ah[3] = AH[SW(mw + mrow + 8, k0 + 4)];
            al[0] = AL[SW(mw + mrow,     k0)];
            al[1] = AL[SW(mw + mrow + 8, k0)];
            al[2] = AL[SW(mw + mrow,     k0 + 4)];
            al[3] = AL[SW(mw + mrow + 8, k0 + 4)];
#pragma unroll
            for (int t = 0; t < 6; t++) {
                const int n = t * 8 + mrow;
                uint32_t bh0 = BH[SW(n, k0)];
                uint32_t bh1 = BH[SW(n, k0 + 4)];
                uint32_t bl0 = BL[SW(n, k0)];
                uint32_t bl1 = BL[SW(n, k0 + 4)];
                mma_tf32(acc[t], ah, bh0, bh1);
                mma_tf32(acc[t], ah, bl0, bl1);
                mma_tf32(acc[t], al, bh0, bh1);
            }
        }
        __syncthreads();
        if (ch + 1 < NCH) {
            sts_chunk(smem + ((ch + 1) & 1) * BUF_U32);
            __syncthreads();
        }
    }

    // ---- epilogue: write partials ----
    // acc[t]: c0 -> (m0, n0), c1 -> (m0, n0+1), c2 -> (m0+8, n0), c3 -> (m0+8, n0+1)
    {
        const int m0 = m_base + wid * 16 + (lane >> 2);
        const int m1 = m0 + 8;
        const int b0r = m0 / HW2, hw0 = m0 - b0r * HW2;
        const int b1r = m1 / HW2, hw1 = m1 - b1r * HW2;
        float* base0 = g_part + ((size_t)(blockIdx.y * MAXB + b0r) * O_REAL) * HW2 + hw0;
        float* base1 = g_part + ((size_t)(blockIdx.y * MAXB + b1r) * O_REAL) * HW2 + hw1;
#pragma unroll
        for (int t = 0; t < 6; t++) {
            const int n0 = t * 8 + 2 * (lane & 3);
            base0[(size_t)n0 * HW2]       = acc[t][0];
            base0[(size_t)(n0 + 1) * HW2] = acc[t][1];
            base1[(size_t)n0 * HW2]       = acc[t][2];
            base1[(size_t)(n0 + 1) * HW2] = acc[t][3];
        }
    }
}

// ---------------------------------------------------------------------------
// Kernel B: per-batch epilogue. Sums K-split partials (+ bias), then
// gmp -> log_softmax -> saliency -> second FC -> log_softmax.
// ---------------------------------------------------------------------------
__global__ void __launch_bounds__(256) wsl_final_kernel(
    const float* __restrict__ down_b,
    const float* __restrict__ fc_b,
    float* __restrict__ out,
    int B)
{
    __shared__ float xc[O_REAL * HW2];
    __shared__ float gmp[32];
    __shared__ float xout[8];
    __shared__ float red[16 * 8];
    __shared__ float psum[16];

    const int b = blockIdx.x;
    const int tid = threadIdx.x;

    for (int i = tid; i < O_REAL * HW2; i += 256) {
        int o = i / HW2;
        float s = g_part[((size_t)b * O_REAL) * HW2 + i]
                + g_part[((size_t)(MAXB + b) * O_REAL) * HW2 + i];
        if (o < 32) s += down_b[o];
        xc[i] = s;
    }
    __syncthreads();

    if (tid < 32) {
        float m = -INFINITY;
        for (int hw = 0; hw < HW2; hw++) m = fmaxf(m, xc[tid * HW2 + hw]);
        gmp[tid] = m;
    }
    __syncthreads();

    if (tid == 0) {
        float sc[8];
        float mx = -INFINITY;
        for (int j = 0; j < 8; j++) {
            sc[j] = 0.25f * (gmp[4 * j] + gmp[4 * j + 1] + gmp[4 * j + 2] + gmp[4 * j + 3]);
            mx = fmaxf(mx, sc[j]);
        }
        float se = 0.f;
        for (int j = 0; j < 8; j++) se += expf(sc[j] - mx);
        float lse = mx + logf(se);
        for (int j = 0; j < 8; j++) {
            float v = sc[j] - lse;
            xout[j] = v;
            out[(size_t)b * 8 + j] = v;
        }
    }
    __syncthreads();

    float v[16];
    if (tid < HW2) {
        float sal = 0.f;
#pragma unroll
        for (int j = 0; j < 8; j++) {
            float cls = xc[(4 * j) * HW2 + tid] + xc[(4 * j + 1) * HW2 + tid] +
                        xc[(4 * j + 2) * HW2 + tid] + xc[(4 * j + 3) * HW2 + tid];
            sal += xout[j] * cls;
        }
        sal *= (1.f / 32.f);
#pragma unroll
        for (int j = 0; j < 8; j++) {
            v[j]     = xc[(32 + j) * HW2 + tid];
            v[8 + j] = sal * xc[(40 + j) * HW2 + tid];
        }
    } else {
#pragma unroll
        for (int k = 0; k < 16; k++) v[k] = 0.f;
    }
#pragma unroll
    for (int off = 16; off > 0; off >>= 1) {
#pragma unroll
        for (int k = 0; k < 16; k++)
            v[k] += __shfl_down_sync(0xffffffffu, v[k], off);
    }
    const int w = tid >> 5, lane = tid & 31;
    if (lane == 0) {
#pragma unroll
        for (int k = 0; k < 16; k++) red[k * 8 + w] = v[k];
    }
    __syncthreads();
    if (tid < 16) {
        float s = 0.f;
#pragma unroll
        for (int ww = 0; ww < 8; ww++) s += red[tid * 8 + ww];
        psum[tid] = s;
    }
    __syncthreads();

    if (tid == 0) {
        float lg[8];
        float mx = -INFINITY;
        for (int j = 0; j < 8; j++) {
            lg[j] = (psum[j] + psum[8 + j]) * (1.f / 196.f) + fc_b[j];
            mx = fmaxf(mx, lg[j]);
        }
        float se = 0.f;
        for (int j = 0; j < 8; j++) se += expf(lg[j] - mx);
        float lse = mx + logf(se);
        for (int j = 0; j < 8; j++)
            out[(size_t)B * 8 + (size_t)b * 8 + j] = lg[j] - lse;
    }
}

// ---------------------------------------------------------------------------
extern "C" void kernel_launch(void* const* d_in, const int* in_sizes, int n_in,
                              void* d_out, int out_size)
{
    const float* x      = (const float*)d_in[0];
    const float* down_w = (const float*)d_in[1];
    const float* down_b = (const float*)d_in[2];
    const float* fc_w   = (const float*)d_in[3];
    const float* fc_b   = (const float*)d_in[4];
    float* out = (float*)d_out;

    int B = in_sizes[0] / (C_TOT * HW2);   // 64

    static bool attr_set = false;
    if (!attr_set) {
        cudaFuncSetAttribute(wsl_mma_kernel,
                             cudaFuncAttributeMaxDynamicSharedMemorySize, SMEM_BYTES);
        attr_set = true;
    }

    dim3 gridA(MTILES, KSPLIT);
    wsl_mma_kernel<<<gridA, 128, SMEM_BYTES>>>(x, down_w, fc_w);
    wsl_final_kernel<<<B, 256>>>(down_b, fc_b, out, B);
}

// round 4
// speedup vs baseline: 2.2867x; 1.3366x over previous
#include <cuda_runtime.h>
#include <cuda_bf16.h>
#include <cstdint>
#include <math.h>

// ---------------------------------------------------------------------------
// Problem constants
// ---------------------------------------------------------------------------
#define C_TOT   2048
#define HW2     196
#define O_REAL  48
#define MAXB    64
#define M_TILE  64
#define MTILES  196          // 12544 / 64
#define KSPLIT  2
#define K_PER   (C_TOT / KSPLIT)   // 1024
#define KC      32
#define NCH     (K_PER / KC)       // 32
#define RS      20           // smem row stride in u32 words (16 data + 4 pad)

// K-split partial GEMM outputs: [KSPLIT][B][48][196]  (4.8 MB)
__device__ float g_part[(size_t)KSPLIT * MAXB * O_REAL * HW2];

// SMEM layout (u32 words per buffer): AH[64*20] AL[64*20] BH[48*20] BL[48*20]
#define AH_OFF  0
#define AL_OFF  1280
#define BH_OFF  2560
#define BL_OFF  3520
#define BUF_U32 4480

__device__ __forceinline__ void mma_bf16(float* c, const uint32_t* a,
                                         uint32_t b0, uint32_t b1) {
    asm volatile(
        "mma.sync.aligned.m16n8k16.row.col.f32.bf16.bf16.f32 "
        "{%0,%1,%2,%3}, {%4,%5,%6,%7}, {%8,%9}, {%0,%1,%2,%3};"
        : "+f"(c[0]), "+f"(c[1]), "+f"(c[2]), "+f"(c[3])
        : "r"(a[0]), "r"(a[1]), "r"(a[2]), "r"(a[3]), "r"(b0), "r"(b1));
}

// pack two bf16 residuals: low half = first arg
__device__ __forceinline__ uint32_t pack_lo_bf16(float l0, float l1) {
    uint32_t r;
    asm("cvt.rn.bf16x2.f32 %0, %1, %2;" : "=r"(r) : "f"(l1), "f"(l0));
    return r;
}

// hi = truncated-bf16 pair: (v1.hi16 << 16) | v0.hi16
__device__ __forceinline__ uint32_t pack_hi_trunc(uint32_t u0, uint32_t u1) {
    return __byte_perm(u0, u1, 0x7632);
}

// ---------------------------------------------------------------------------
// Kernel A: bf16 3-split GEMM  part[ks][m][o] = sum_{k in split} x[m,k] W[o,k]
// Grid (196, 2), 128 threads. Warp w: m rows [w*16, w*16+16), all 48 n.
// ---------------------------------------------------------------------------
__global__ void __launch_bounds__(128) wsl_mma_kernel(
    const float* __restrict__ x,
    const float* __restrict__ down_w,
    const float* __restrict__ fc_w)
{
    __shared__ __align__(16) uint32_t smem[2 * BUF_U32];   // 35.8 KB

    const int tid  = threadIdx.x;
    const int wid  = tid >> 5;
    const int lane = tid & 31;
    const int m_base  = blockIdx.x * M_TILE;
    const int ks_base = blockIdx.y * K_PER;

    // ---- A staging: thread owns row m = tid&63, k-halves per aq0 ----
    const int am  = tid & 63;
    const int aq0 = tid >> 6;                 // 0/1 -> k offset 16*aq0
    {
        // nothing
    }
    const int mg = m_base + am;
    const int bb = mg / HW2;
    const int hw = mg - bb * HW2;
    const float* a_base = x + ((size_t)bb * C_TOT) * HW2 + hw;
    const uint32_t a_sts = (uint32_t)(am * RS + aq0 * 8);   // 8 contiguous words

    // ---- B staging: thread owns (n = tid>>3 + 16i, quad q = tid&7) ----
    const int bq  = tid & 7;
    const int bn0 = tid >> 3;                 // 0..15
    const float* b_ptr[3];
    uint32_t b_sts[3];
#pragma unroll
    for (int i = 0; i < 3; i++) {
        int n = bn0 + 16 * i;
        const float* wr;
        if (n < 32)      wr = down_w + (size_t)n * C_TOT;
        else if (n < 40) wr = fc_w + (size_t)(n - 32) * (2 * C_TOT);
        else             wr = fc_w + (size_t)(n - 40) * (2 * C_TOT) + C_TOT;
        b_ptr[i] = wr + bq * 4;
        b_sts[i] = (uint32_t)(n * RS + bq * 2);
    }

    float acc[6][4];
#pragma unroll
    for (int t = 0; t < 6; t++)
#pragma unroll
        for (int j = 0; j < 4; j++) acc[t][j] = 0.f;

    float4 areg[4], breg[3];

    auto ldg_chunk = [&](int ch) {
        const int kb = ks_base + ch * KC;
#pragma unroll
        for (int i = 0; i < 4; i++) {
            const float* p = a_base + (size_t)(kb + aq0 * 16 + i * 4) * HW2;
            areg[i].x = __ldg(p);
            areg[i].y = __ldg(p + HW2);
            areg[i].z = __ldg(p + 2 * HW2);
            areg[i].w = __ldg(p + 3 * HW2);
        }
#pragma unroll
        for (int i = 0; i < 3; i++)
            breg[i] = *reinterpret_cast<const float4*>(b_ptr[i] + kb);
    };

    auto sts_chunk = [&](uint32_t* buf) {
        uint32_t hiw[8], low[8];
#pragma unroll
        for (int i = 0; i < 4; i++) {
            uint32_t u0 = __float_as_uint(areg[i].x), u1 = __float_as_uint(areg[i].y);
            uint32_t u2 = __float_as_uint(areg[i].z), u3 = __float_as_uint(areg[i].w);
            hiw[2 * i]     = pack_hi_trunc(u0, u1);
            hiw[2 * i + 1] = pack_hi_trunc(u2, u3);
            float l0 = areg[i].x - __uint_as_float(u0 & 0xffff0000u);
            float l1 = areg[i].y - __uint_as_float(u1 & 0xffff0000u);
            float l2 = areg[i].z - __uint_as_float(u2 & 0xffff0000u);
            float l3 = areg[i].w - __uint_as_float(u3 & 0xffff0000u);
            low[2 * i]     = pack_lo_bf16(l0, l1);
            low[2 * i + 1] = pack_lo_bf16(l2, l3);
        }
        *reinterpret_cast<uint4*>(buf + AH_OFF + a_sts)     = make_uint4(hiw[0], hiw[1], hiw[2], hiw[3]);
        *reinterpret_cast<uint4*>(buf + AH_OFF + a_sts + 4) = make_uint4(hiw[4], hiw[5], hiw[6], hiw[7]);
        *reinterpret_cast<uint4*>(buf + AL_OFF + a_sts)     = make_uint4(low[0], low[1], low[2], low[3]);
        *reinterpret_cast<uint4*>(buf + AL_OFF + a_sts + 4) = make_uint4(low[4], low[5], low[6], low[7]);
#pragma unroll
        for (int i = 0; i < 3; i++) {
            uint32_t u0 = __float_as_uint(breg[i].x), u1 = __float_as_uint(breg[i].y);
            uint32_t u2 = __float_as_uint(breg[i].z), u3 = __float_as_uint(breg[i].w);
            uint32_t h01 = pack_hi_trunc(u0, u1);
            uint32_t h23 = pack_hi_trunc(u2, u3);
            float l0 = breg[i].x - __uint_as_float(u0 & 0xffff0000u);
            float l1 = breg[i].y - __uint_as_float(u1 & 0xffff0000u);
            float l2 = breg[i].z - __uint_as_float(u2 & 0xffff0000u);
            float l3 = breg[i].w - __uint_as_float(u3 & 0xffff0000u);
            *reinterpret_cast<uint2*>(buf + BH_OFF + b_sts[i]) = make_uint2(h01, h23);
            *reinterpret_cast<uint2*>(buf + BL_OFF + b_sts[i]) =
                make_uint2(pack_lo_bf16(l0, l1), pack_lo_bf16(l2, l3));
        }
    };

    // prologue
    ldg_chunk(0);
    sts_chunk(smem);
    __syncthreads();

    const int mrow = lane >> 2;   // 0..7 (A row group, B n group)
    const int kcol = lane & 3;    // 0..3 (kp within half)
    const int mw   = wid * 16;

    for (int ch = 0; ch < NCH; ch++) {
        if (ch + 1 < NCH) ldg_chunk(ch + 1);

        const uint32_t* buf = smem + (ch & 1) * BUF_U32;
        const uint32_t* AH = buf + AH_OFF;
        const uint32_t* AL = buf + AL_OFF;
        const uint32_t* BH = buf + BH_OFF;
        const uint32_t* BL = buf + BL_OFF;

#pragma unroll
        for (int s = 0; s < 2; s++) {
            const int kp = s * 8 + kcol;
            uint32_t ah[4], al[4];
            ah[0] = AH[(mw + mrow) * RS + kp];
            ah[1] = AH[(mw + mrow + 8) * RS + kp];
            ah[2] = AH[(mw + mrow) * RS + kp + 4];
            ah[3] = AH[(mw + mrow + 8) * RS + kp + 4];
            al[0] = AL[(mw + mrow) * RS + kp];
            al[1] = AL[(mw + mrow + 8) * RS + kp];
            al[2] = AL[(mw + mrow) * RS + kp + 4];
            al[3] = AL[(mw + mrow + 8) * RS + kp + 4];
#pragma unroll
            for (int t = 0; t < 6; t++) {
                const int n = t * 8 + mrow;
                uint32_t bh0 = BH[n * RS + kp];
                uint32_t bh1 = BH[n * RS + kp + 4];
                uint32_t bl0 = BL[n * RS + kp];
                uint32_t bl1 = BL[n * RS + kp + 4];
                mma_bf16(acc[t], ah, bh0, bh1);
                mma_bf16(acc[t], ah, bl0, bl1);
                mma_bf16(acc[t], al, bh0, bh1);
            }
        }
        __syncthreads();
        if (ch + 1 < NCH) {
            sts_chunk(const_cast<uint32_t*>(smem) + ((ch + 1) & 1) * BUF_U32);
            __syncthreads();
        }
    }

    // ---- epilogue: write partials ----
    {
        const int m0 = m_base + mw + mrow;
        const int m1 = m0 + 8;
        const int b0r = m0 / HW2, hw0 = m0 - b0r * HW2;
        const int b1r = m1 / HW2, hw1 = m1 - b1r * HW2;
        float* base0 = g_part + ((size_t)(blockIdx.y * MAXB + b0r) * O_REAL) * HW2 + hw0;
        float* base1 = g_part + ((size_t)(blockIdx.y * MAXB + b1r) * O_REAL) * HW2 + hw1;
#pragma unroll
        for (int t = 0; t < 6; t++) {
            const int n0 = t * 8 + 2 * kcol;
            base0[(size_t)n0 * HW2]       = acc[t][0];
            base0[(size_t)(n0 + 1) * HW2] = acc[t][1];
            base1[(size_t)n0 * HW2]       = acc[t][2];
            base1[(size_t)(n0 + 1) * HW2] = acc[t][3];
        }
    }
}

// ---------------------------------------------------------------------------
// Kernel B: per-batch epilogue, 512 threads.
// ---------------------------------------------------------------------------
__global__ void __launch_bounds__(512) wsl_final_kernel(
    const float* __restrict__ down_b,
    const float* __restrict__ fc_b,
    float* __restrict__ out,
    int B)
{
    __shared__ float xc[O_REAL * HW2];    // 9408 floats
    __shared__ float gmp[32];
    __shared__ float xout[8];
    __shared__ float red[16 * 16];
    __shared__ float psum[16];

    const int b = blockIdx.x;
    const int tid = threadIdx.x;
    const int w = tid >> 5, lane = tid & 31;

    // Sum the two K-split partials (+ bias), vectorized (196 % 4 == 0).
    {
        const float4* p0 = reinterpret_cast<const float4*>(g_part + ((size_t)b * O_REAL) * HW2);
        const float4* p1 = reinterpret_cast<const float4*>(g_part + ((size_t)(MAXB + b) * O_REAL) * HW2);
        float4* dst = reinterpret_cast<float4*>(xc);
        for (int i = tid; i < (O_REAL * HW2) / 4; i += 512) {
            float4 a = __ldg(p0 + i);
            float4 c = __ldg(p1 + i);
            int o = i / 49;                      // (i*4)/196
            float bias = (o < 32) ? down_b[o] : 0.f;
            dst[i] = make_float4(a.x + c.x + bias, a.y + c.y + bias,
                                 a.z + c.z + bias, a.w + c.w + bias);
        }
    }
    __syncthreads();

    // GMP: warp w handles maps o=w and o=w+16 (w<16 always, 16 warps).
    {
        float m1 = -INFINITY, m2 = -INFINITY;
        for (int h = lane; h < HW2; h += 32) {
            m1 = fmaxf(m1, xc[w * HW2 + h]);
            m2 = fmaxf(m2, xc[(w + 16) * HW2 + h]);
        }
#pragma unroll
        for (int off = 16; off > 0; off >>= 1) {
            m1 = fmaxf(m1, __shfl_down_sync(0xffffffffu, m1, off));
            m2 = fmaxf(m2, __shfl_down_sync(0xffffffffu, m2, off));
        }
        if (lane == 0) { gmp[w] = m1; gmp[w + 16] = m2; }
    }
    __syncthreads();

    if (tid == 0) {
        float sc[8];
        float mx = -INFINITY;
        for (int j = 0; j < 8; j++) {
            sc[j] = 0.25f * (gmp[4 * j] + gmp[4 * j + 1] + gmp[4 * j + 2] + gmp[4 * j + 3]);
            mx = fmaxf(mx, sc[j]);
        }
        float se = 0.f;
        for (int j = 0; j < 8; j++) se += expf(sc[j] - mx);
        float lse = mx + logf(se);
        for (int j = 0; j < 8; j++) {
            float v = sc[j] - lse;
            xout[j] = v;
            out[(size_t)b * 8 + j] = v;
        }
    }
    __syncthreads();

    float v[16];
    if (tid < HW2) {
        float sal = 0.f;
#pragma unroll
        for (int j = 0; j < 8; j++) {
            float cls = xc[(4 * j) * HW2 + tid] + xc[(4 * j + 1) * HW2 + tid] +
                        xc[(4 * j + 2) * HW2 + tid] + xc[(4 * j + 3) * HW2 + tid];
            sal += xout[j] * cls;
        }
        sal *= (1.f / 32.f);
#pragma unroll
        for (int j = 0; j < 8; j++) {
            v[j]     = xc[(32 + j) * HW2 + tid];
            v[8 + j] = sal * xc[(40 + j) * HW2 + tid];
        }
    } else {
#pragma unroll
        for (int k = 0; k < 16; k++) v[k] = 0.f;
    }
#pragma unroll
    for (int off = 16; off > 0; off >>= 1) {
#pragma unroll
        for (int k = 0; k < 16; k++)
            v[k] += __shfl_down_sync(0xffffffffu, v[k], off);
    }
    if (lane == 0) {
#pragma unroll
        for (int k = 0; k < 16; k++) red[k * 16 + w] = v[k];
    }
    __syncthreads();
    if (tid < 16) {
        float s = 0.f;
#pragma unroll
        for (int ww = 0; ww < 16; ww++) s += red[tid * 16 + ww];
        psum[tid] = s;
    }
    __syncthreads();

    if (tid == 0) {
        float lg[8];
        float mx = -INFINITY;
        for (int j = 0; j < 8; j++) {
            lg[j] = (psum[j] + psum[8 + j]) * (1.f / 196.f) + fc_b[j];
            mx = fmaxf(mx, lg[j]);
        }
        float se = 0.f;
        for (int j = 0; j < 8; j++) se += expf(lg[j] - mx);
        float lse = mx + logf(se);
        for (int j = 0; j < 8; j++)
            out[(size_t)B * 8 + (size_t)b * 8 + j] = lg[j] - lse;
    }
}

// ---------------------------------------------------------------------------
extern "C" void kernel_launch(void* const* d_in, const int* in_sizes, int n_in,
                              void* d_out, int out_size)
{
    const float* x      = (const float*)d_in[0];
    const float* down_w = (const float*)d_in[1];
    const float* down_b = (const float*)d_in[2];
    const float* fc_w   = (const float*)d_in[3];
    const float* fc_b   = (const float*)d_in[4];
    float* out = (float*)d_out;

    int B = in_sizes[0] / (C_TOT * HW2);   // 64

    dim3 gridA(MTILES, KSPLIT);
    wsl_mma_kernel<<<gridA, 128>>>(x, down_w, fc_w);
    wsl_final_kernel<<<B, 512>>>(down_b, fc_b, out, B);
}

// round 5
// speedup vs baseline: 3.2862x; 1.4371x over previous
#include <cuda_runtime.h>
#include <cuda_bf16.h>
#include <cstdint>
#include <math.h>

// ---------------------------------------------------------------------------
// Problem constants
// ---------------------------------------------------------------------------
#define C_TOT   2048
#define HW2     196
#define O_REAL  48
#define MAXB    64
#define M_TILE  64
#define MTILES  196           // 12544 / 64
#define KSPLIT  2
#define K_PER   (C_TOT / KSPLIT)   // 1024
#define KC      128           // k per smem chunk
#define NCH     (K_PER / KC)  // 8
#define NSTEP   (K_PER / 32)  // 32 k32 steps per CTA

// B smem/global image: per chunk, 48 rows x 144 u32 words (128 data + 16 pad)
#define ROWW    144
#define BUFW    (48 * ROWW)          // 6912 words per buffer
#define CHUNK_BYTES (BUFW * 4)       // 27648
#define CP_UNITS (BUFW / 4)          // 1728 16B units
#define SMEM_BYTES (2 * CHUNK_BYTES) // 55296

// Scratch
__device__ float    g_part[(size_t)KSPLIT * MAXB * O_REAL * HW2];     // 4.8 MB
__device__ uint32_t g_wprep[(size_t)16 * BUFW];                        // 442 KB

// ---------------------------------------------------------------------------
// helpers
// ---------------------------------------------------------------------------
__device__ __forceinline__ void mma_bf16(float* c, const uint32_t* a,
                                         uint32_t b0, uint32_t b1) {
    asm volatile(
        "mma.sync.aligned.m16n8k16.row.col.f32.bf16.bf16.f32 "
        "{%0,%1,%2,%3}, {%4,%5,%6,%7}, {%8,%9}, {%0,%1,%2,%3};"
        : "+f"(c[0]), "+f"(c[1]), "+f"(c[2]), "+f"(c[3])
        : "r"(a[0]), "r"(a[1]), "r"(a[2]), "r"(a[3]), "r"(b0), "r"(b1));
}
__device__ __forceinline__ uint32_t pack_lo_bf16(float l0, float l1) {
    uint32_t r;
    asm("cvt.rn.bf16x2.f32 %0, %1, %2;" : "=r"(r) : "f"(l1), "f"(l0));
    return r;
}
__device__ __forceinline__ uint32_t pack_hi_trunc(uint32_t u0, uint32_t u1) {
    return __byte_perm(u0, u1, 0x7632);
}
__device__ __forceinline__ uint32_t smem_u32addr(const void* p) {
    uint32_t a;
    asm("{ .reg .u64 t; cvta.to.shared.u64 t, %1; cvt.u32.u64 %0, t; }" : "=r"(a) : "l"(p));
    return a;
}
__device__ __forceinline__ void cp_async16(uint32_t saddr, const void* gaddr) {
    asm volatile("cp.async.cg.shared.global [%0], [%1], 16;" :: "r"(saddr), "l"(gaddr));
}

// ---------------------------------------------------------------------------
// Prep kernel: convert W (48 x 2048) into hi/lo bf16 interleaved, permuted
// per-chunk SMEM image. Task = (chunk ci, n, s-group): 16*48*8 = 6144 tasks.
// Group layout (16 words): [h0,h4,l0,l4, h1,h5,l1,l5, h2,h6,l2,l6, h3,h7,l3,l7]
// ---------------------------------------------------------------------------
__global__ void __launch_bounds__(256) wsl_prep_kernel(
    const float* __restrict__ down_w,
    const float* __restrict__ fc_w)
{
    int idx = blockIdx.x * 256 + threadIdx.x;
    if (idx >= 16 * 48 * 8) return;
    int ci = idx / 384;
    int r  = idx - ci * 384;
    int n  = r >> 3;
    int s  = r & 7;

    const float* wr;
    if (n < 32)      wr = down_w + (size_t)n * C_TOT;
    else if (n < 40) wr = fc_w + (size_t)(n - 32) * (2 * C_TOT);
    else             wr = fc_w + (size_t)(n - 40) * (2 * C_TOT) + C_TOT;

    const float* src = wr + ci * KC + s * 16;
    float f[16];
#pragma unroll
    for (int q = 0; q < 4; q++) {
        float4 v = *reinterpret_cast<const float4*>(src + 4 * q);
        f[4 * q] = v.x; f[4 * q + 1] = v.y; f[4 * q + 2] = v.z; f[4 * q + 3] = v.w;
    }
    uint32_t* dst = g_wprep + ((size_t)ci * 48 + n) * ROWW + s * 16;
#pragma unroll
    for (int pp = 0; pp < 8; pp++) {
        uint32_t u0 = __float_as_uint(f[2 * pp]);
        uint32_t u1 = __float_as_uint(f[2 * pp + 1]);
        uint32_t hi = pack_hi_trunc(u0, u1);
        float l0 = f[2 * pp]     - __uint_as_float(u0 & 0xffff0000u);
        float l1 = f[2 * pp + 1] - __uint_as_float(u1 & 0xffff0000u);
        uint32_t lo = pack_lo_bf16(l0, l1);
        int base = 4 * (pp & 3) + (pp >> 2);
        dst[base]     = hi;
        dst[base + 2] = lo;
    }
}

// ---------------------------------------------------------------------------
// Kernel A: bf16 3-split GEMM, A direct-to-register, B via cp.async.
// Grid (196, 2), 128 threads.
// ---------------------------------------------------------------------------
__global__ void __launch_bounds__(128) wsl_mma_kernel(const float* __restrict__ x)
{
    extern __shared__ __align__(16) uint32_t smem[];
    const uint32_t sbase = smem_u32addr(smem);

    const int tid  = threadIdx.x;
    const int wid  = tid >> 5;
    const int lane = tid & 31;
    const int g    = lane >> 2;    // 0..7
    const int c    = lane & 3;     // 0..3
    const int m_base  = blockIdx.x * M_TILE;
    const int ks      = blockIdx.y;
    const int ks_base = ks * K_PER;
    const int ch0     = ks * NCH;  // global chunk base in g_wprep

    // two A rows this lane owns
    const int m0 = m_base + wid * 16 + g;
    const int m1 = m0 + 8;
    const int b0r = m0 / HW2, hw0 = m0 - b0r * HW2;
    const int b1r = m1 / HW2, hw1 = m1 - b1r * HW2;
    const float* pA0 = x + ((size_t)b0r * C_TOT) * HW2 + hw0;
    const float* pA1 = x + ((size_t)b1r * C_TOT) * HW2 + hw1;

    float acc[6][4];
#pragma unroll
    for (int t = 0; t < 6; t++)
#pragma unroll
        for (int j = 0; j < 4; j++) acc[t][j] = 0.f;

    // raw A prefetch buffers (distance 2): [parity][row][8 k-values]
    float r0[2][8], r1[2][8];

    auto ldgA = [&](int s, int p) {
        const int kb = ks_base + s * 32 + 2 * c;
#pragma unroll
        for (int j = 0; j < 2; j++) {
            const size_t k = (size_t)(kb + 16 * j);
            r0[p][4 * j]     = __ldg(pA0 + k * HW2);
            r0[p][4 * j + 1] = __ldg(pA0 + (k + 1) * HW2);
            r0[p][4 * j + 2] = __ldg(pA0 + (k + 8) * HW2);
            r0[p][4 * j + 3] = __ldg(pA0 + (k + 9) * HW2);
            r1[p][4 * j]     = __ldg(pA1 + k * HW2);
            r1[p][4 * j + 1] = __ldg(pA1 + (k + 1) * HW2);
            r1[p][4 * j + 2] = __ldg(pA1 + (k + 8) * HW2);
            r1[p][4 * j + 3] = __ldg(pA1 + (k + 9) * HW2);
        }
    };

    auto issueB = [&](int ch) {
        const char* src = reinterpret_cast<const char*>(
            g_wprep + (size_t)(ch0 + ch) * BUFW);
        const uint32_t dst = sbase + (uint32_t)((ch & 1) * CHUNK_BYTES);
        for (int u = tid; u < CP_UNITS; u += 128)
            cp_async16(dst + u * 16, src + u * 16);
        asm volatile("cp.async.commit_group;" ::: "memory");
    };

    // prologue
    ldgA(0, 0);
    ldgA(1, 1);
    issueB(0);

    for (int ch = 0; ch < NCH; ch++) {
        if (ch + 1 < NCH) {
            issueB(ch + 1);
            asm volatile("cp.async.wait_group 1;" ::: "memory");
        } else {
            asm volatile("cp.async.wait_group 0;" ::: "memory");
        }
        __syncthreads();

        const uint32_t* buf = smem + (ch & 1) * BUFW;

#pragma unroll
        for (int kk = 0; kk < 4; kk++) {
            const int s = ch * 4 + kk;
            const int p = s & 1;

            // convert raw -> frags for 2 sub-chunks
            uint32_t ah[2][4], al[2][4];
#pragma unroll
            for (int j = 0; j < 2; j++) {
                const float* q0 = &r0[p][4 * j];
                const float* q1 = &r1[p][4 * j];
                uint32_t u;
                u = __float_as_uint(q0[0]);
                uint32_t u01 = u, m01 = u & 0xffff0000u;
                u = __float_as_uint(q0[1]);
                uint32_t u02 = u, m02 = u & 0xffff0000u;
                ah[j][0] = pack_hi_trunc(u01, u02);
                al[j][0] = pack_lo_bf16(q0[0] - __uint_as_float(m01),
                                        q0[1] - __uint_as_float(m02));
                u = __float_as_uint(q1[0]);
                uint32_t u11 = u, m11 = u & 0xffff0000u;
                u = __float_as_uint(q1[1]);
                uint32_t u12 = u, m12 = u & 0xffff0000u;
                ah[j][1] = pack_hi_trunc(u11, u12);
                al[j][1] = pack_lo_bf16(q1[0] - __uint_as_float(m11),
                                        q1[1] - __uint_as_float(m12));
                u = __float_as_uint(q0[2]);
                uint32_t u21 = u, m21 = u & 0xffff0000u;
                u = __float_as_uint(q0[3]);
                uint32_t u22 = u, m22 = u & 0xffff0000u;
                ah[j][2] = pack_hi_trunc(u21, u22);
                al[j][2] = pack_lo_bf16(q0[2] - __uint_as_float(m21),
                                        q0[3] - __uint_as_float(m22));
                u = __float_as_uint(q1[2]);
                uint32_t u31 = u, m31 = u & 0xffff0000u;
                u = __float_as_uint(q1[3]);
                uint32_t u32_ = u, m32 = u & 0xffff0000u;
                ah[j][3] = pack_hi_trunc(u31, u32_);
                al[j][3] = pack_lo_bf16(q1[2] - __uint_as_float(m31),
                                        q1[3] - __uint_as_float(m32));
            }

            // prefetch A for step s+2
            if (s + 2 < NSTEP) ldgA(s + 2, p);

            // MMAs: 2 sub-chunks x 6 n-tiles x 3 splits
#pragma unroll
            for (int j = 0; j < 2; j++) {
                const int s16 = kk * 2 + j;
#pragma unroll
                for (int t = 0; t < 6; t++) {
                    const uint4 bw = *reinterpret_cast<const uint4*>(
                        buf + (t * 8 + g) * ROWW + s16 * 16 + 4 * c);
                    mma_bf16(acc[t], ah[j], bw.x, bw.y);   // hi*hi
                    mma_bf16(acc[t], ah[j], bw.z, bw.w);   // hi*lo
                    mma_bf16(acc[t], al[j], bw.x, bw.y);   // lo*hi
                }
            }
        }
        __syncthreads();
    }

    // ---- epilogue: write partials ----
    {
        float* base0 = g_part + ((size_t)(ks * MAXB + b0r) * O_REAL) * HW2 + hw0;
        float* base1 = g_part + ((size_t)(ks * MAXB + b1r) * O_REAL) * HW2 + hw1;
#pragma unroll
        for (int t = 0; t < 6; t++) {
            const int n0 = t * 8 + 2 * c;
            base0[(size_t)n0 * HW2]       = acc[t][0];
            base0[(size_t)(n0 + 1) * HW2] = acc[t][1];
            base1[(size_t)n0 * HW2]       = acc[t][2];
            base1[(size_t)(n0 + 1) * HW2] = acc[t][3];
        }
    }
}

// ---------------------------------------------------------------------------
// Kernel B: per-batch epilogue, 512 threads.
// ---------------------------------------------------------------------------
__global__ void __launch_bounds__(512) wsl_final_kernel(
    const float* __restrict__ down_b,
    const float* __restrict__ fc_b,
    float* __restrict__ out,
    int B)
{
    __shared__ float xc[O_REAL * HW2];
    __shared__ float gmp[32];
    __shared__ float xout[8];
    __shared__ float red[16 * 16];
    __shared__ float psum[16];

    const int b = blockIdx.x;
    const int tid = threadIdx.x;
    const int w = tid >> 5, lane = tid & 31;

    {
        const float4* p0 = reinterpret_cast<const float4*>(g_part + ((size_t)b * O_REAL) * HW2);
        const float4* p1 = reinterpret_cast<const float4*>(g_part + ((size_t)(MAXB + b) * O_REAL) * HW2);
        float4* dst = reinterpret_cast<float4*>(xc);
        for (int i = tid; i < (O_REAL * HW2) / 4; i += 512) {
            float4 a = __ldg(p0 + i);
            float4 c = __ldg(p1 + i);
            int o = i / 49;
            float bias = (o < 32) ? down_b[o] : 0.f;
            dst[i] = make_float4(a.x + c.x + bias, a.y + c.y + bias,
                                 a.z + c.z + bias, a.w + c.w + bias);
        }
    }
    __syncthreads();

    {
        float m1 = -INFINITY, m2 = -INFINITY;
        for (int h = lane; h < HW2; h += 32) {
            m1 = fmaxf(m1, xc[w * HW2 + h]);
            m2 = fmaxf(m2, xc[(w + 16) * HW2 + h]);
        }
#pragma unroll
        for (int off = 16; off > 0; off >>= 1) {
            m1 = fmaxf(m1, __shfl_down_sync(0xffffffffu, m1, off));
            m2 = fmaxf(m2, __shfl_down_sync(0xffffffffu, m2, off));
        }
        if (lane == 0) { gmp[w] = m1; gmp[w + 16] = m2; }
    }
    __syncthreads();

    if (tid == 0) {
        float sc[8];
        float mx = -INFINITY;
        for (int j = 0; j < 8; j++) {
            sc[j] = 0.25f * (gmp[4 * j] + gmp[4 * j + 1] + gmp[4 * j + 2] + gmp[4 * j + 3]);
            mx = fmaxf(mx, sc[j]);
        }
        float se = 0.f;
        for (int j = 0; j < 8; j++) se += expf(sc[j] - mx);
        float lse = mx + logf(se);
        for (int j = 0; j < 8; j++) {
            float v = sc[j] - lse;
            xout[j] = v;
            out[(size_t)b * 8 + j] = v;
        }
    }
    __syncthreads();

    float v[16];
    if (tid < HW2) {
        float sal = 0.f;
#pragma unroll
        for (int j = 0; j < 8; j++) {
            float cls = xc[(4 * j) * HW2 + tid] + xc[(4 * j + 1) * HW2 + tid] +
                        xc[(4 * j + 2) * HW2 + tid] + xc[(4 * j + 3) * HW2 + tid];
            sal += xout[j] * cls;
        }
        sal *= (1.f / 32.f);
#pragma unroll
        for (int j = 0; j < 8; j++) {
            v[j]     = xc[(32 + j) * HW2 + tid];
            v[8 + j] = sal * xc[(40 + j) * HW2 + tid];
        }
    } else {
#pragma unroll
        for (int k = 0; k < 16; k++) v[k] = 0.f;
    }
#pragma unroll
    for (int off = 16; off > 0; off >>= 1) {
#pragma unroll
        for (int k = 0; k < 16; k++)
            v[k] += __shfl_down_sync(0xffffffffu, v[k], off);
    }
    if (lane == 0) {
#pragma unroll
        for (int k = 0; k < 16; k++) red[k * 16 + w] = v[k];
    }
    __syncthreads();
    if (tid < 16) {
        float s = 0.f;
#pragma unroll
        for (int ww = 0; ww < 16; ww++) s += red[tid * 16 + ww];
        psum[tid] = s;
    }
    __syncthreads();

    if (tid == 0) {
        float lg[8];
        float mx = -INFINITY;
        for (int j = 0; j < 8; j++) {
            lg[j] = (psum[j] + psum[8 + j]) * (1.f / 196.f) + fc_b[j];
            mx = fmaxf(mx, lg[j]);
        }
        float se = 0.f;
        for (int j = 0; j < 8; j++) se += expf(lg[j] - mx);
        float lse = mx + logf(se);
        for (int j = 0; j < 8; j++)
            out[(size_t)B * 8 + (size_t)b * 8 + j] = lg[j] - lse;
    }
}

// ---------------------------------------------------------------------------
extern "C" void kernel_launch(void* const* d_in, const int* in_sizes, int n_in,
                              void* d_out, int out_size)
{
    const float* x      = (const float*)d_in[0];
    const float* down_w = (const float*)d_in[1];
    const float* down_b = (const float*)d_in[2];
    const float* fc_w   = (const float*)d_in[3];
    const float* fc_b   = (const float*)d_in[4];
    float* out = (float*)d_out;

    int B = in_sizes[0] / (C_TOT * HW2);   // 64

    static bool attr_set = false;
    if (!attr_set) {
        cudaFuncSetAttribute(wsl_mma_kernel,
                             cudaFuncAttributeMaxDynamicSharedMemorySize, SMEM_BYTES);
        attr_set = true;
    }

    wsl_prep_kernel<<<24, 256>>>(down_w, fc_w);
    dim3 gridA(MTILES, KSPLIT);
    wsl_mma_kernel<<<gridA, 128, SMEM_BYTES>>>(x);
    wsl_final_kernel<<<B, 512>>>(down_b, fc_b, out, B);
}